// round 3
// baseline (speedup 1.0000x reference)
#include <cuda_runtime.h>
#include <cuda_bf16.h>

// GraphSAGE 2-layer + linear head, fp32.
// Pipeline per launch:
//   detect(edge dtype) -> clear(deg) -> hist(dst) -> scan -> scatter(csr)
//   aggregate(x)   -> mean ; gemm_dual(mean, x , Wl1,Wr1,bl1, relu) -> h1
//   aggregate(h1)  -> mean ; gemm_dual(mean, h1, Wl2,Wr2,bl2, relu) -> h2
//   out_gemm(h2, Wout, bout) -> out [N,40]
// All scratch in __device__ globals; only kernel launches enqueued.
// Edge index dtype (int32 vs int64) is detected ON DEVICE: JAX without x64
// silently demotes jnp.int64 randint to int32, so we must handle both.

#define MAXN 100000
#define MAXE 1600000
#define DIM  128

__device__ int    g_is64;
__device__ int    g_deg[MAXN];
__device__ int    g_off[MAXN + 1];
__device__ int    g_cur[MAXN];
__device__ int    g_csr[MAXE];
__device__ float4 g_mean4[(size_t)MAXN * 32];   // float4 => guaranteed 16B align
__device__ float4 g_h14[(size_t)MAXN * 32];
__device__ float4 g_h24[(size_t)MAXN * 32];

// ---------------------------------------------------------------------------
// -1. dtype detection: int64 data has zero high words at odd int32 positions
// ---------------------------------------------------------------------------
__global__ void detect_kernel(const int* __restrict__ w, int e) {
    if (threadIdx.x == 0 && blockIdx.x == 0) {
        int is64 = 1;
        int nchk = (e < 256) ? e : 256;
        for (int i = 0; i < nchk; i++) {
            if (w[2 * i + 1] != 0) { is64 = 0; break; }
        }
        g_is64 = is64;
    }
}

// ---------------------------------------------------------------------------
// 0. clear degree counters
// ---------------------------------------------------------------------------
__global__ void clear_deg_kernel(int n) {
    int i = blockIdx.x * blockDim.x + threadIdx.x;
    if (i < n) g_deg[i] = 0;
}

// ---------------------------------------------------------------------------
// 1. histogram of dst
// ---------------------------------------------------------------------------
__global__ void hist_kernel(const void* __restrict__ ei, int e, int n) {
    int i = blockIdx.x * blockDim.x + threadIdx.x;
    if (i >= e) return;
    int d = g_is64 ? (int)((const long long*)ei)[e + i]
                   : ((const int*)ei)[e + i];
    if ((unsigned)d < (unsigned)n) atomicAdd(&g_deg[d], 1);
}

// ---------------------------------------------------------------------------
// 2. single-block exclusive scan (n up to 100k, 1024 threads, chunked)
// ---------------------------------------------------------------------------
__global__ void scan_kernel(int n) {
    __shared__ int wsum[32];
    __shared__ int carry_s;
    int tid = threadIdx.x, lane = tid & 31, wid = tid >> 5;
    if (tid == 0) carry_s = 0;
    __syncthreads();
    for (int base = 0; base < n; base += 1024) {
        int i = base + tid;
        int v = (i < n) ? g_deg[i] : 0;
        int s = v;
        #pragma unroll
        for (int d = 1; d < 32; d <<= 1) {
            int t = __shfl_up_sync(0xffffffffu, s, d);
            if (lane >= d) s += t;
        }
        if (lane == 31) wsum[wid] = s;
        __syncthreads();
        if (wid == 0) {
            int ws = wsum[lane];
            #pragma unroll
            for (int d = 1; d < 32; d <<= 1) {
                int t = __shfl_up_sync(0xffffffffu, ws, d);
                if (lane >= d) ws += t;
            }
            wsum[lane] = ws;
        }
        __syncthreads();
        int carry = carry_s;
        int warp_base = (wid > 0) ? wsum[wid - 1] : 0;
        int excl = carry + warp_base + s - v;
        if (i < n) { g_off[i] = excl; g_cur[i] = excl; }
        int total = wsum[31];
        __syncthreads();
        if (tid == 0) carry_s += total;
        __syncthreads();
    }
    if (threadIdx.x == 0) g_off[n] = carry_s;
}

// ---------------------------------------------------------------------------
// 3. scatter edges into CSR buckets (by dst), payload = src
// ---------------------------------------------------------------------------
__global__ void scatter_kernel(const void* __restrict__ ei, int e, int n) {
    int i = blockIdx.x * blockDim.x + threadIdx.x;
    if (i >= e) return;
    int s, d;
    if (g_is64) {
        s = (int)((const long long*)ei)[i];
        d = (int)((const long long*)ei)[e + i];
    } else {
        s = ((const int*)ei)[i];
        d = ((const int*)ei)[e + i];
    }
    if ((unsigned)d >= (unsigned)n || (unsigned)s >= (unsigned)n) return;
    int pos = atomicAdd(&g_cur[d], 1);
    g_csr[pos] = s;
}

// ---------------------------------------------------------------------------
// 4. mean aggregation: one warp per dst node, lane holds float4 (4 feats)
// ---------------------------------------------------------------------------
__global__ void aggregate_kernel(const float4* __restrict__ feat,
                                 float4* __restrict__ outp, int n) {
    int w = (blockIdx.x * blockDim.x + threadIdx.x) >> 5;
    int lane = threadIdx.x & 31;
    if (w >= n) return;
    int s0 = g_off[w], s1 = g_off[w + 1];
    float4 a0 = make_float4(0.f, 0.f, 0.f, 0.f);
    float4 a1 = make_float4(0.f, 0.f, 0.f, 0.f);
    int e = s0;
    for (; e + 2 <= s1; e += 2) {
        int i0 = g_csr[e], i1 = g_csr[e + 1];
        float4 v0 = feat[(size_t)i0 * 32 + lane];
        float4 v1 = feat[(size_t)i1 * 32 + lane];
        a0.x += v0.x; a0.y += v0.y; a0.z += v0.z; a0.w += v0.w;
        a1.x += v1.x; a1.y += v1.y; a1.z += v1.z; a1.w += v1.w;
    }
    if (e < s1) {
        int i0 = g_csr[e];
        float4 v0 = feat[(size_t)i0 * 32 + lane];
        a0.x += v0.x; a0.y += v0.y; a0.z += v0.z; a0.w += v0.w;
    }
    int deg = s1 - s0;
    float inv = 1.0f / (float)(deg > 1 ? deg : 1);
    float4 r;
    r.x = (a0.x + a1.x) * inv;
    r.y = (a0.y + a1.y) * inv;
    r.z = (a0.z + a1.z) * inv;
    r.w = (a0.w + a1.w) * inv;
    outp[(size_t)w * 32 + lane] = r;
}

// ---------------------------------------------------------------------------
// 5. dual GEMM: C = act(A1 @ W1^T + A2 @ W2^T + bias)   (K=128 each, N=128)
//    64-row tiles, 256 threads, TM=4 x TN=8 register tiling.
// ---------------------------------------------------------------------------
__global__ __launch_bounds__(256) void gemm_dual_kernel(
    const float* __restrict__ A1, const float* __restrict__ A2,
    const float* __restrict__ W1, const float* __restrict__ W2,
    const float* __restrict__ bias, float* __restrict__ C,
    int n, int do_relu) {
    __shared__ __align__(16) float As[64][16];
    __shared__ __align__(16) float Ws[16][132]; // [kk][j], pitch 132 (528B, 16B-mult)

    int tid = threadIdx.x;
    int ty = tid >> 4;       // 0..15 row group (4 rows each)
    int tx = tid & 15;       // 0..15 col group (8 cols each)
    int row0 = blockIdx.x * 64;

    float acc[4][8];
    #pragma unroll
    for (int r = 0; r < 4; r++)
        #pragma unroll
        for (int c = 0; c < 8; c++) acc[r][c] = 0.f;

    for (int kt = 0; kt < 256; kt += 16) {
        const float* A = (kt < 128) ? A1 : A2;
        const float* W = (kt < 128) ? W1 : W2;
        int kb = kt & 127;
        // A tile: 64x16, one float4 per thread
        {
            int r = tid >> 2;
            int kq = (tid & 3) << 2;
            int gr = row0 + r;
            float4 v = make_float4(0.f, 0.f, 0.f, 0.f);
            if (gr < n)
                v = *reinterpret_cast<const float4*>(&A[(size_t)gr * 128 + kb + kq]);
            *reinterpret_cast<float4*>(&As[r][kq]) = v;
        }
        // W tile transposed: Ws[kk][j] = W[j][kb+kk]
        #pragma unroll
        for (int it = 0; it < 8; it++) {
            int idx = tid + it * 256;
            int kk = idx & 15;
            int j = idx >> 4;
            Ws[kk][j] = W[j * 128 + kb + kk];
        }
        __syncthreads();
        #pragma unroll
        for (int kk = 0; kk < 16; kk++) {
            float a[4];
            #pragma unroll
            for (int r = 0; r < 4; r++) a[r] = As[ty * 4 + r][kk];
            float4 wv0 = *reinterpret_cast<const float4*>(&Ws[kk][tx * 8]);
            float4 wv1 = *reinterpret_cast<const float4*>(&Ws[kk][tx * 8 + 4]);
            float w[8] = {wv0.x, wv0.y, wv0.z, wv0.w, wv1.x, wv1.y, wv1.z, wv1.w};
            #pragma unroll
            for (int r = 0; r < 4; r++)
                #pragma unroll
                for (int c = 0; c < 8; c++) acc[r][c] += a[r] * w[c];
        }
        __syncthreads();
    }
    float b[8];
    #pragma unroll
    for (int c = 0; c < 8; c++) b[c] = bias[tx * 8 + c];
    #pragma unroll
    for (int r = 0; r < 4; r++) {
        int gr = row0 + ty * 4 + r;
        if (gr < n) {
            float o[8];
            #pragma unroll
            for (int c = 0; c < 8; c++) {
                float v = acc[r][c] + b[c];
                o[c] = (do_relu && v < 0.f) ? 0.f : v;
            }
            *reinterpret_cast<float4*>(&C[(size_t)gr * 128 + tx * 8]) =
                make_float4(o[0], o[1], o[2], o[3]);
            *reinterpret_cast<float4*>(&C[(size_t)gr * 128 + tx * 8 + 4]) =
                make_float4(o[4], o[5], o[6], o[7]);
        }
    }
}

// ---------------------------------------------------------------------------
// 6. output head: out[N,40] = h2 @ Wout^T + bout
// ---------------------------------------------------------------------------
__global__ __launch_bounds__(240) void out_gemm_kernel(
    const float* __restrict__ h, const float* __restrict__ Wout,
    const float* __restrict__ bout, float* __restrict__ out, int n) {
    __shared__ float sh[6][128];
    __shared__ float sw[40][129];
    int tid = threadIdx.x;
    for (int idx = tid; idx < 40 * 128; idx += 240) {
        int j = idx >> 7, k = idx & 127;
        sw[j][k] = Wout[idx];
    }
    int node0 = blockIdx.x * 6;
    for (int idx = tid; idx < 6 * 128; idx += 240) {
        int r = idx >> 7, k = idx & 127;
        int gn = node0 + r;
        sh[r][k] = (gn < n) ? h[(size_t)gn * 128 + k] : 0.f;
    }
    __syncthreads();
    int r = tid / 40, j = tid % 40;
    int node = node0 + r;
    if (node < n) {
        float acc = 0.f;
        #pragma unroll 8
        for (int k = 0; k < 128; k++) acc += sh[r][k] * sw[j][k];
        out[(size_t)node * 40 + j] = acc + bout[j];
    }
}

// ---------------------------------------------------------------------------
extern "C" void kernel_launch(void* const* d_in, const int* in_sizes, int n_in,
                              void* d_out, int out_size) {
    const float* x = (const float*)d_in[0];
    const void* ei = d_in[1];
    const float* Wl1 = (const float*)d_in[2];
    const float* bl1 = (const float*)d_in[3];
    const float* Wr1 = (const float*)d_in[4];
    const float* Wl2 = (const float*)d_in[5];
    const float* bl2 = (const float*)d_in[6];
    const float* Wr2 = (const float*)d_in[7];
    const float* Wout = (const float*)d_in[8];
    const float* bout = (const float*)d_in[9];
    float* out = (float*)d_out;

    int n = in_sizes[0] / DIM;
    int e = in_sizes[1] / 2;

    static float* mean_f = nullptr;
    static float* h1_f = nullptr;
    static float* h2_f = nullptr;
    if (!mean_f) {  // symbol lookup only (no allocation, no stream ops)
        void* p;
        cudaGetSymbolAddress(&p, g_mean4); mean_f = (float*)p;
        cudaGetSymbolAddress(&p, g_h14);   h1_f   = (float*)p;
        cudaGetSymbolAddress(&p, g_h24);   h2_f   = (float*)p;
    }

    int eb = (e + 255) / 256;
    int nb = (n + 255) / 256;
    detect_kernel<<<1, 32>>>((const int*)ei, e);
    clear_deg_kernel<<<nb, 256>>>(n);
    hist_kernel<<<eb, 256>>>(ei, e, n);
    scan_kernel<<<1, 1024>>>(n);
    scatter_kernel<<<eb, 256>>>(ei, e, n);

    int ab = (n + 7) / 8;          // 8 warps (256 threads) per block
    int gb = (n + 63) / 64;
    int ob = (n + 5) / 6;

    // Layer 1
    aggregate_kernel<<<ab, 256>>>((const float4*)x, (float4*)mean_f, n);
    gemm_dual_kernel<<<gb, 256>>>(mean_f, x, Wl1, Wr1, bl1, h1_f, n, 1);
    // Layer 2
    aggregate_kernel<<<ab, 256>>>((const float4*)h1_f, (float4*)mean_f, n);
    gemm_dual_kernel<<<gb, 256>>>(mean_f, h1_f, Wl2, Wr2, bl2, h2_f, n, 1);
    // Head
    out_gemm_kernel<<<ob, 240>>>(h2_f, Wout, bout, out, n);
}